// round 12
// baseline (speedup 1.0000x reference)
#include <cuda_runtime.h>
#include <cuda_bf16.h>
#include <cstdint>

#define NUM_CLASSES 10
#define THREADS 512
#define ESTAGE   4096                      // elements per stage
#define NS       3                         // pipeline stages
#define TILE_BYTES  (ESTAGE * 4)           // 16 KB per array per stage
#define STAGE_BYTES (3 * TILE_BYTES)       // 48 KB
#define TILES_BYTES (NS * STAGE_BYTES)     // 144 KB
#define ACC_OFF   TILES_BYTES
#define ACC_BYTES (NUM_CLASSES * THREADS * 4)   // 20 KB
#define MBAR_OFF  (ACC_OFF + ACC_BYTES)
#define SMEM_TOTAL (MBAR_OFF + 2 * NS * 8 + 16)

// Global scratch (allocation-free rule). Zero at load; last block re-zeros.
__device__ float        g_sum[NUM_CLASSES];
__device__ float        g_cnt[NUM_CLASSES];
__device__ unsigned int g_ticket;

// ---------- PTX helpers ----------
__device__ __forceinline__ uint32_t smem_u32(const void* p) {
    uint32_t a;
    asm("{ .reg .u64 t; cvta.to.shared.u64 t, %1; cvt.u32.u64 %0, t; }" : "=r"(a) : "l"(p));
    return a;
}
__device__ __forceinline__ void mbar_init(uint32_t b, uint32_t cnt) {
    asm volatile("mbarrier.init.shared.b64 [%0], %1;" :: "r"(b), "r"(cnt) : "memory");
}
__device__ __forceinline__ void mbar_expect_tx(uint32_t b, uint32_t bytes) {
    asm volatile("mbarrier.arrive.expect_tx.shared.b64 _, [%0], %1;" :: "r"(b), "r"(bytes) : "memory");
}
__device__ __forceinline__ void mbar_arrive(uint32_t b) {
    asm volatile("mbarrier.arrive.shared.b64 _, [%0];" :: "r"(b) : "memory");
}
__device__ __forceinline__ void mbar_wait_acq(uint32_t b, uint32_t ph) {
    uint32_t done;
    asm volatile("{\n\t.reg .pred p;\n\t"
                 "mbarrier.try_wait.parity.acquire.cta.shared::cta.b64 p, [%1], %2;\n\t"
                 "selp.b32 %0, 1, 0, p;\n\t}"
                 : "=r"(done) : "r"(b), "r"(ph) : "memory");
    if (!done) {
        asm volatile("{\n\t.reg .pred P1;\n\t"
                     "W0_%=:\n\t"
                     "mbarrier.try_wait.parity.acquire.cta.shared::cta.b64 P1, [%0], %1, 0x989680;\n\t"
                     "@P1 bra.uni WD_%=;\n\t"
                     "bra.uni W0_%=;\n\t"
                     "WD_%=:\n\t}" :: "r"(b), "r"(ph) : "memory");
    }
}
__device__ __forceinline__ void mbar_wait_rlx(uint32_t b, uint32_t ph) {
    uint32_t done;
    asm volatile("{\n\t.reg .pred p;\n\t"
                 "mbarrier.try_wait.parity.relaxed.cta.shared::cta.b64 p, [%1], %2, 0x989680;\n\t"
                 "selp.b32 %0, 1, 0, p;\n\t}"
                 : "=r"(done) : "r"(b), "r"(ph) : "memory");
    if (!done) {
        asm volatile("{\n\t.reg .pred P1;\n\t"
                     "W1_%=:\n\t"
                     "mbarrier.try_wait.parity.relaxed.cta.shared::cta.b64 P1, [%0], %1, 0x989680;\n\t"
                     "@P1 bra.uni WE_%=;\n\t"
                     "bra.uni W1_%=;\n\t"
                     "WE_%=:\n\t}" :: "r"(b), "r"(ph) : "memory");
    }
}
__device__ __forceinline__ void bulk_g2s(uint32_t dst, const void* src, uint32_t bytes, uint32_t mbar) {
    asm volatile("cp.async.bulk.shared::cta.global.mbarrier::complete_tx::bytes [%0], [%1], %2, [%3];"
                 :: "r"(dst), "l"(src), "r"(bytes), "r"(mbar) : "memory");
}

// scatter sq-err into per-thread smem column; counts packed 12-bit x5 in two u64s
__device__ __forceinline__ void accum_one(float* __restrict__ accp,
                                          unsigned long long& cA,
                                          unsigned long long& cB,
                                          float o, float t, int m) {
    int   c     = __float2int_rz(t);         // targets are exact ints 0..9
    bool  valid = (m == 1);
    float d     = o - t;
    float sq    = valid ? d * d : 0.0f;
    accp[c * THREADS] += sq;                 // invalid adds 0.0f: harmless
    bool lo = (c < 5);
    int  f  = lo ? c : (c - 5);
    unsigned long long inc = valid ? (1ull << (12 * f)) : 0ull;
    if (lo) cA += inc; else cB += inc;
}

__global__ __launch_bounds__(THREADS, 1)
void loss_tma_kernel(const float* __restrict__ o,
                     const float* __restrict__ t,
                     const int*   __restrict__ m,
                     int n, float* __restrict__ out) {
    extern __shared__ __align__(16) char sm[];
    float* acc = (float*)(sm + ACC_OFF);
    __shared__ bool s_is_last;

    const int tid  = threadIdx.x;
    const int lane = tid & 31;
    const uint32_t smb    = smem_u32(sm);
    const uint32_t full0  = smb + MBAR_OFF;
    const uint32_t empty0 = smb + MBAR_OFF + NS * 8;

    #pragma unroll
    for (int c = 0; c < NUM_CLASSES; c++) acc[c * THREADS + tid] = 0.0f;
    if (tid == 0) {
        #pragma unroll
        for (int s = 0; s < NS; s++) {
            mbar_init(full0 + 8 * s, 1);               // expect_tx arrive only
            mbar_init(empty0 + 8 * s, THREADS / 32);   // one arrive per warp
        }
        asm volatile("fence.proxy.async.shared::cta;" ::: "memory");
    }
    __syncthreads();

    const int grid = gridDim.x;
    const int b    = blockIdx.x;
    const int S    = n / ESTAGE;      // full stages (n = 2^24 -> 4096, no tail)

    // producer prologue: fill the ring
    if (tid == 0) {
        #pragma unroll
        for (int p = 0; p < NS; p++) {
            int sg = b + p * grid;
            if (sg < S) {
                mbar_expect_tx(full0 + 8 * p, STAGE_BYTES);
                size_t eoff = (size_t)sg * ESTAGE;
                uint32_t dst = smb + p * STAGE_BYTES;
                bulk_g2s(dst,                  o + eoff, TILE_BYTES, full0 + 8 * p);
                bulk_g2s(dst + TILE_BYTES,     t + eoff, TILE_BYTES, full0 + 8 * p);
                bulk_g2s(dst + 2 * TILE_BYTES, m + eoff, TILE_BYTES, full0 + 8 * p);
            }
        }
    }

    unsigned long long cA = 0ull, cB = 0ull;
    float* accp = acc + tid;

    int slot = 0;
    uint32_t phase = 0;
    for (int sg = b; sg < S; sg += grid) {
        mbar_wait_acq(full0 + 8 * slot, phase);

        const char* base = sm + slot * STAGE_BYTES;
        const float4* to = (const float4*)(base);
        const float4* tt = (const float4*)(base + TILE_BYTES);
        const int4*   tm = (const int4*)  (base + 2 * TILE_BYTES);
        float4 o0 = to[tid], o1 = to[tid + THREADS];
        float4 t0 = tt[tid], t1 = tt[tid + THREADS];
        int4   m0 = tm[tid], m1 = tm[tid + THREADS];

        accum_one(accp, cA, cB, o0.x, t0.x, m0.x);
        accum_one(accp, cA, cB, o0.y, t0.y, m0.y);
        accum_one(accp, cA, cB, o0.z, t0.z, m0.z);
        accum_one(accp, cA, cB, o0.w, t0.w, m0.w);
        accum_one(accp, cA, cB, o1.x, t1.x, m1.x);
        accum_one(accp, cA, cB, o1.y, t1.y, m1.y);
        accum_one(accp, cA, cB, o1.z, t1.z, m1.z);
        accum_one(accp, cA, cB, o1.w, t1.w, m1.w);

        __syncwarp();
        if (lane == 0) mbar_arrive(empty0 + 8 * slot);   // warp-aggregated

        if (tid == 0) {
            int s_issue = sg + NS * grid;
            if (s_issue < S) {
                mbar_wait_rlx(empty0 + 8 * slot, phase); // all warps freed slot
                mbar_expect_tx(full0 + 8 * slot, STAGE_BYTES);
                size_t eoff = (size_t)s_issue * ESTAGE;
                uint32_t dst = smb + slot * STAGE_BYTES;
                bulk_g2s(dst,                  o + eoff, TILE_BYTES, full0 + 8 * slot);
                bulk_g2s(dst + TILE_BYTES,     t + eoff, TILE_BYTES, full0 + 8 * slot);
                bulk_g2s(dst + 2 * TILE_BYTES, m + eoff, TILE_BYTES, full0 + 8 * slot);
            }
        }
        if (++slot == NS) { slot = 0; phase ^= 1; }
    }

    // generic scalar tail (empty for n = 2^24, kept for safety)
    for (int j = S * ESTAGE + b * THREADS + tid; j < n; j += grid * THREADS)
        accum_one(accp, cA, cB, o[j], t[j], m[j]);

    __syncthreads();

    // overlay counts on the (now dead) tile region
    float* s_cnt = (float*)sm;
    #pragma unroll
    for (int c = 0; c < NUM_CLASSES; c++) {
        unsigned long long w = (c < 5) ? cA : cB;
        s_cnt[c * THREADS + tid] =
            (float)((unsigned)(w >> (12 * (c < 5 ? c : c - 5))) & 0xFFFu);
    }
    __syncthreads();

    // block tree-reduction over 512 thread columns
    for (int s = THREADS / 2; s > 0; s >>= 1) {
        if (tid < s) {
            #pragma unroll
            for (int c = 0; c < NUM_CLASSES; c++) {
                acc  [c * THREADS + tid] += acc  [c * THREADS + tid + s];
                s_cnt[c * THREADS + tid] += s_cnt[c * THREADS + tid + s];
            }
        }
        __syncthreads();
    }

    if (tid < NUM_CLASSES) {
        atomicAdd(&g_sum[tid], acc[tid * THREADS]);
        atomicAdd(&g_cnt[tid], s_cnt[tid * THREADS]);
        __threadfence();
    }
    __syncthreads();

    if (tid == 0) {
        unsigned int tk = atomicAdd(&g_ticket, 1u);
        s_is_last = (tk == (unsigned int)gridDim.x - 1u);
    }
    __syncthreads();

    // last block finalizes and resets scratch for next graph replay
    if (s_is_last && tid == 0) {
        __threadfence();
        float loss = 0.0f;
        #pragma unroll
        for (int c = 0; c < NUM_CLASSES; c++) {
            float s  = atomicAdd(&g_sum[c], 0.0f);
            float nn = atomicAdd(&g_cnt[c], 0.0f);
            float le = (nn > 0.0f) ? (s / fmaxf(nn, 1.0f)) : 0.0f;
            out[1 + c] = le;                 // loss_each
            out[1 + NUM_CLASSES + c] = nn;   // class_n
            loss = fmaf(0.1f, le, loss);     // WEIGHT = 0.1 each
            g_sum[c] = 0.0f;
            g_cnt[c] = 0.0f;
        }
        out[0] = loss;
        g_ticket = 0u;
    }
}

extern "C" void kernel_launch(void* const* d_in, const int* in_sizes, int n_in,
                              void* d_out, int out_size) {
    const float* outputs = (const float*)d_in[0];
    const float* targets = (const float*)d_in[1];
    const int*   mask    = (const int*)d_in[2];
    int n = in_sizes[0];

    int dev = 0, nsm = 148;
    cudaGetDevice(&dev);
    cudaDeviceGetAttribute(&nsm, cudaDevAttrMultiProcessorCount, dev);

    cudaFuncSetAttribute(loss_tma_kernel,
                         cudaFuncAttributeMaxDynamicSharedMemorySize, SMEM_TOTAL);

    loss_tma_kernel<<<nsm, THREADS, SMEM_TOTAL>>>(outputs, targets, mask, n,
                                                  (float*)d_out);
}

// round 14
// speedup vs baseline: 1.0225x; 1.0225x over previous
#include <cuda_runtime.h>
#include <cuda_bf16.h>
#include <cstdint>

#define NUM_CLASSES 10
#define THREADS 256
#define NWARP   (THREADS / 32)
#define CTAS_PER_SM 6
#define BLOCKS (148 * CTAS_PER_SM)    // 888

// Global scratch (allocation-free rule). Zero at module load; last block
// re-zeros after finalize -> deterministic across graph replays.
__device__ float        g_sum[NUM_CLASSES];
__device__ float        g_cnt[NUM_CLASSES];
__device__ unsigned int g_ticket;

// 256-bit global loads (sm_100+): one request, 32 bytes.
__device__ __forceinline__ void ldg256_f(const float* __restrict__ p, float* v) {
    asm volatile("ld.global.nc.v8.f32 {%0,%1,%2,%3,%4,%5,%6,%7}, [%8];"
                 : "=f"(v[0]), "=f"(v[1]), "=f"(v[2]), "=f"(v[3]),
                   "=f"(v[4]), "=f"(v[5]), "=f"(v[6]), "=f"(v[7])
                 : "l"(p));
}
__device__ __forceinline__ void ldg256_i(const int* __restrict__ p, int* v) {
    asm volatile("ld.global.nc.v8.b32 {%0,%1,%2,%3,%4,%5,%6,%7}, [%8];"
                 : "=r"(v[0]), "=r"(v[1]), "=r"(v[2]), "=r"(v[3]),
                   "=r"(v[4]), "=r"(v[5]), "=r"(v[6]), "=r"(v[7])
                 : "l"(p));
}

// scatter sq-err into this thread's smem column; counts packed 12-bit x5
// in two u64 registers (classes 0-4 -> cA, 5-9 -> cB).
// targets are integer 0..9 everywhere (even where mask==0), so invalid
// elements add 0.0f to their real class: harmless. Counts only when valid.
__device__ __forceinline__ void accum_one(float* __restrict__ accp,
                                          unsigned long long& cA,
                                          unsigned long long& cB,
                                          float o, float t, int m) {
    int   c     = __float2int_rz(t);
    bool  valid = (m == 1);
    float d     = o - t;
    float sq    = valid ? d * d : 0.0f;
    accp[c * THREADS] += sq;
    bool lo = (c < 5);
    int  f  = lo ? c : (c - 5);
    unsigned long long inc = valid ? (1ull << (12 * f)) : 0ull;
    if (lo) cA += inc; else cB += inc;
}

__global__ __launch_bounds__(THREADS, CTAS_PER_SM)
void loss_v8_kernel(const float* __restrict__ o,
                    const float* __restrict__ t,
                    const int*   __restrict__ m,
                    int n, float* __restrict__ out) {
    __shared__ float acc[NUM_CLASSES * THREADS];      // 10 KB
    __shared__ float warp_out[NWARP * 2 * NUM_CLASSES];
    __shared__ bool  s_is_last;

    const int tid  = threadIdx.x;
    const int lane = tid & 31;
    const int wid  = tid >> 5;

    #pragma unroll
    for (int c = 0; c < NUM_CLASSES; c++)
        acc[c * THREADS + tid] = 0.0f;
    __syncthreads();

    float* accp = acc + tid;
    unsigned long long cA = 0ull, cB = 0ull;

    // main loop: 8 elements/thread/iter via 3x LDG.256 (32B requests)
    const int n8      = n >> 3;                 // groups of 8
    const int gtid    = blockIdx.x * THREADS + tid;
    const int gstride = gridDim.x * THREADS;

    for (int g = gtid; g < n8; g += gstride) {
        const int base = g << 3;
        float ov[8], tv[8];
        int   mv[8];
        ldg256_f(o + base, ov);
        ldg256_f(t + base, tv);
        ldg256_i(m + base, mv);
        #pragma unroll
        for (int k = 0; k < 8; k++)
            accum_one(accp, cA, cB, ov[k], tv[k], mv[k]);
    }
    // scalar tail (n % 8) — empty for n = 2^24, kept for generality
    for (int j = (n8 << 3) + gtid; j < n; j += gstride)
        accum_one(accp, cA, cB, o[j], t[j], m[j]);

    __syncthreads();   // all scatters into acc columns complete

    // ---- fast reduction tail: warp shfl, then one cross-warp pass ----
    float v[2 * NUM_CLASSES];
    #pragma unroll
    for (int c = 0; c < NUM_CLASSES; c++) {
        v[c] = acc[c * THREADS + tid];
        unsigned long long w = (c < 5) ? cA : cB;
        v[NUM_CLASSES + c] =
            (float)((unsigned)(w >> (12 * (c < 5 ? c : c - 5))) & 0xFFFu);
    }
    #pragma unroll
    for (int off = 16; off > 0; off >>= 1) {
        #pragma unroll
        for (int c = 0; c < 2 * NUM_CLASSES; c++)
            v[c] += __shfl_down_sync(0xFFFFFFFFu, v[c], off);
    }
    if (lane == 0) {
        #pragma unroll
        for (int c = 0; c < 2 * NUM_CLASSES; c++)
            warp_out[wid * 2 * NUM_CLASSES + c] = v[c];
    }
    __syncthreads();

    if (tid < 2 * NUM_CLASSES) {
        float r = 0.0f;
        #pragma unroll
        for (int w = 0; w < NWARP; w++)
            r += warp_out[w * 2 * NUM_CLASSES + tid];
        if (tid < NUM_CLASSES) atomicAdd(&g_sum[tid], r);
        else                   atomicAdd(&g_cnt[tid - NUM_CLASSES], r);
        __threadfence();
    }
    __syncthreads();

    if (tid == 0) {
        unsigned int tk = atomicAdd(&g_ticket, 1u);
        s_is_last = (tk == (unsigned int)gridDim.x - 1u);
    }
    __syncthreads();

    // last-arriving block finalizes and resets scratch for the next replay
    if (s_is_last && tid == 0) {
        __threadfence();
        float loss = 0.0f;
        #pragma unroll
        for (int c = 0; c < NUM_CLASSES; c++) {
            float s  = atomicAdd(&g_sum[c], 0.0f);
            float nn = atomicAdd(&g_cnt[c], 0.0f);
            float le = (nn > 0.0f) ? (s / fmaxf(nn, 1.0f)) : 0.0f;
            out[1 + c] = le;                 // loss_each
            out[1 + NUM_CLASSES + c] = nn;   // class_n
            loss = fmaf(0.1f, le, loss);     // WEIGHT = 0.1 each
            g_sum[c] = 0.0f;
            g_cnt[c] = 0.0f;
        }
        out[0] = loss;
        g_ticket = 0u;
    }
}

extern "C" void kernel_launch(void* const* d_in, const int* in_sizes, int n_in,
                              void* d_out, int out_size) {
    const float* outputs = (const float*)d_in[0];
    const float* targets = (const float*)d_in[1];
    const int*   mask    = (const int*)d_in[2];
    int n = in_sizes[0];

    loss_v8_kernel<<<BLOCKS, THREADS>>>(outputs, targets, mask, n,
                                        (float*)d_out);
}